// round 2
// baseline (speedup 1.0000x reference)
#include <cuda_runtime.h>

// Problem constants
#define BB      8
#define DIN     1024
#define TT      2048
#define KCB     8192
#define CD      8
#define NTOK    (BB*TT)            // 16384
#define NSPLIT  16
#define CPS     (KCB/NSPLIT)       // 512 codes per split
#define TOKBLK  1024               // tokens per search CTA (256 thr * 4 tok)

// Output buffer layout (float32, concatenated tuple)
#define OUT_OFF   0
#define LOSS_OFF  (BB*DIN*TT)                 // 16777216
#define IDX_OFF   (LOSS_OFF + 16)             // 16777232
#define ZE_OFF    (IDX_OFF + NTOK)            // 16793616

// Scratch (device globals — no allocation allowed)
__device__ float              g_zep[8u*BB*CD*TT];     // 4 MB partial in-proj [dc][b][o][t]
__device__ float              g_enc[(size_t)NTOK*CD]; // normalized encodings, token-major
__device__ unsigned long long g_cbdup[(size_t)KCB*9]; // per code: 8x {c,c} + {-c2/2,-c2/2}
__device__ unsigned long long g_wdup[(size_t)DIN*9];  // per out-row: 8x {w,w} + {b,b}
__device__ float              g_partS[NSPLIT*NTOK];
__device__ int                g_partI[NSPLIT*NTOK];
__device__ int                g_idx[NTOK];

// ---- packed f32x2 helpers ----
__device__ __forceinline__ unsigned long long pack2(float lo, float hi) {
    unsigned long long r;
    asm("mov.b64 %0, {%1,%2};" : "=l"(r) : "f"(lo), "f"(hi));
    return r;
}
__device__ __forceinline__ void unpack2(unsigned long long v, float& lo, float& hi) {
    asm("mov.b64 {%0,%1}, %2;" : "=f"(lo), "=f"(hi) : "l"(v));
}
__device__ __forceinline__ unsigned long long fma2(unsigned long long a, unsigned long long b,
                                                   unsigned long long c) {
    unsigned long long d;
    asm("fma.rn.f32x2 %0, %1, %2, %3;" : "=l"(d) : "l"(a), "l"(b), "l"(c));
    return d;
}
__device__ __forceinline__ unsigned long long add2(unsigned long long a, unsigned long long b) {
    unsigned long long d;
    asm("add.rn.f32x2 %0, %1, %2;" : "=l"(d) : "l"(a), "l"(b));
    return d;
}

// ---------------------------------------------------------------------------
// K0: prep — normalize codebook into duplicated-pair table, pack w_out/b_out,
//     zero the loss outputs.
// ---------------------------------------------------------------------------
__global__ void k_prep(const float* __restrict__ cb, const float* __restrict__ w_out,
                       const float* __restrict__ b_out, float* __restrict__ out) {
    int i = blockIdx.x * 256 + threadIdx.x;
    if (i < KCB) {
        float v[CD];
#pragma unroll
        for (int k = 0; k < CD; k++) v[k] = cb[(size_t)i * CD + k];
        float s = 0.0f;
#pragma unroll
        for (int k = 0; k < CD; k++) s += v[k] * v[k];
        float den = fmaxf(__fsqrt_rn(s), 1e-12f);
        float nv[CD];
#pragma unroll
        for (int k = 0; k < CD; k++) nv[k] = __fdiv_rn(v[k], den);
        float c2 = 0.0f;
#pragma unroll
        for (int k = 0; k < CD; k++) c2 += nv[k] * nv[k];
#pragma unroll
        for (int k = 0; k < CD; k++) g_cbdup[(size_t)i * 9 + k] = pack2(nv[k], nv[k]);
        float h = -0.5f * c2;
        g_cbdup[(size_t)i * 9 + 8] = pack2(h, h);
    } else if (i < KCB + DIN) {
        int o = i - KCB;
#pragma unroll
        for (int k = 0; k < CD; k++) {
            float w = w_out[(size_t)o * CD + k];
            g_wdup[(size_t)o * 9 + k] = pack2(w, w);
        }
        float bo = b_out[o];
        g_wdup[(size_t)o * 9 + 8] = pack2(bo, bo);
    } else if (i < KCB + DIN + 16) {
        out[LOSS_OFF + (i - KCB - DIN)] = 0.0f;
    }
}

// ---------------------------------------------------------------------------
// K1: partial in-projection.  grid(T/256, B, 8 d-chunks), 256 threads.
// ---------------------------------------------------------------------------
__global__ void __launch_bounds__(256) k_inproj(const float* __restrict__ z,
                                                const float* __restrict__ w_in) {
    __shared__ float sw[128 * 8];  // [dd][o]
    int tid = threadIdx.x;
    int tb = blockIdx.x, b = blockIdx.y, dc = blockIdx.z;
    for (int i = tid; i < 1024; i += 256) {
        int dd = i >> 3, o = i & 7;
        sw[dd * 8 + o] = w_in[(size_t)o * DIN + dc * 128 + dd];
    }
    __syncthreads();

    int t = tb * 256 + tid;
    float acc[8];
#pragma unroll
    for (int o = 0; o < 8; o++) acc[o] = 0.0f;

    const float* zp = z + ((size_t)b * DIN + (size_t)dc * 128) * TT + t;
#pragma unroll 4
    for (int dd = 0; dd < 128; dd++) {
        float zv = zp[(size_t)dd * TT];
        float4 wA = *reinterpret_cast<const float4*>(&sw[dd * 8]);
        float4 wB = *reinterpret_cast<const float4*>(&sw[dd * 8 + 4]);
        acc[0] += wA.x * zv; acc[1] += wA.y * zv; acc[2] += wA.z * zv; acc[3] += wA.w * zv;
        acc[4] += wB.x * zv; acc[5] += wB.y * zv; acc[6] += wB.z * zv; acc[7] += wB.w * zv;
    }
    float* op = g_zep + ((size_t)(dc * 8 + b) * 8) * TT + t;
#pragma unroll
    for (int o = 0; o < 8; o++) op[(size_t)o * TT] = acc[o];
}

// ---------------------------------------------------------------------------
// K2: reduce partials + bias, write z_e output, L2-normalize into g_enc.
// ---------------------------------------------------------------------------
__global__ void k_reduce(const float* __restrict__ b_in, float* __restrict__ out) {
    int token = blockIdx.x * 256 + threadIdx.x;   // 64 blocks
    int b = token >> 11, t = token & 2047;
    float ze[8];
#pragma unroll
    for (int o = 0; o < 8; o++) {
        float s = 0.0f;
#pragma unroll
        for (int dc = 0; dc < 8; dc++)
            s += g_zep[((size_t)(dc * 8 + b) * 8 + o) * TT + t];
        ze[o] = s + b_in[o];
    }
#pragma unroll
    for (int o = 0; o < 8; o++)
        out[ZE_OFF + ((size_t)b * 8 + o) * TT + t] = ze[o];
    float s2 = 0.0f;
#pragma unroll
    for (int o = 0; o < 8; o++) s2 += ze[o] * ze[o];
    float den = fmaxf(__fsqrt_rn(s2), 1e-12f);
#pragma unroll
    for (int o = 0; o < 8; o++)
        g_enc[(size_t)token * 8 + o] = __fdiv_rn(ze[o], den);
}

// ---------------------------------------------------------------------------
// K3: nearest-code search.  grid(16 token-blocks, 16 code-splits), 256 thr.
// Each thread: 4 tokens (two f32x2 pairs) x 512 codes.
// score = dot(enc_n, cb_n) - 0.5*c2  (argmax == reference argmin of dist)
// ---------------------------------------------------------------------------
__global__ void __launch_bounds__(256) k_search() {
    __shared__ unsigned long long s_cd[CPS][8];
    __shared__ unsigned long long s_c2[CPS];
    int tid = threadIdx.x;
    int cbase = blockIdx.y * CPS;

    for (int i = tid; i < CPS * 9; i += 256) {
        unsigned long long v = g_cbdup[(size_t)cbase * 9 + i];
        int j = i / 9, kk = i - j * 9;
        if (kk < 8) s_cd[j][kk] = v; else s_c2[j] = v;
    }

    int tok0 = blockIdx.x * TOKBLK + tid * 4;
    const float4* ep = reinterpret_cast<const float4*>(&g_enc[(size_t)tok0 * 8]);
    float4 p0 = ep[0], p1 = ep[1], p2 = ep[2], p3 = ep[3];
    float4 p4 = ep[4], p5 = ep[5], p6 = ep[6], p7 = ep[7];
    unsigned long long ea[8], eb[8];
    ea[0] = pack2(p0.x, p2.x); ea[1] = pack2(p0.y, p2.y);
    ea[2] = pack2(p0.z, p2.z); ea[3] = pack2(p0.w, p2.w);
    ea[4] = pack2(p1.x, p3.x); ea[5] = pack2(p1.y, p3.y);
    ea[6] = pack2(p1.z, p3.z); ea[7] = pack2(p1.w, p3.w);
    eb[0] = pack2(p4.x, p6.x); eb[1] = pack2(p4.y, p6.y);
    eb[2] = pack2(p4.z, p6.z); eb[3] = pack2(p4.w, p6.w);
    eb[4] = pack2(p5.x, p7.x); eb[5] = pack2(p5.y, p7.y);
    eb[6] = pack2(p5.z, p7.z); eb[7] = pack2(p5.w, p7.w);

    __syncthreads();

    float best0 = -3.4e38f, best1 = -3.4e38f, best2 = -3.4e38f, best3 = -3.4e38f;
    int bi0 = 0, bi1 = 0, bi2 = 0, bi3 = 0;

#pragma unroll 4
    for (int j = 0; j < CPS; j++) {
        unsigned long long c2p = s_c2[j];
        const ulonglong2* cp = reinterpret_cast<const ulonglong2*>(&s_cd[j][0]);
        ulonglong2 cA = cp[0], cB = cp[1], cC = cp[2], cD = cp[3];

        unsigned long long aA = fma2(ea[0], cA.x, c2p);
        unsigned long long aB = fma2(eb[0], cA.x, c2p);
        aA = fma2(ea[1], cA.y, aA);  aB = fma2(eb[1], cA.y, aB);
        aA = fma2(ea[2], cB.x, aA);  aB = fma2(eb[2], cB.x, aB);
        aA = fma2(ea[3], cB.y, aA);  aB = fma2(eb[3], cB.y, aB);
        aA = fma2(ea[4], cC.x, aA);  aB = fma2(eb[4], cC.x, aB);
        aA = fma2(ea[5], cC.y, aA);  aB = fma2(eb[5], cC.y, aB);
        aA = fma2(ea[6], cD.x, aA);  aB = fma2(eb[6], cD.x, aB);
        aA = fma2(ea[7], cD.y, aA);  aB = fma2(eb[7], cD.y, aB);

        float s0, s1, s2, s3;
        unpack2(aA, s0, s1);
        unpack2(aB, s2, s3);
        if (s0 > best0) { best0 = s0; bi0 = j; }
        if (s1 > best1) { best1 = s1; bi1 = j; }
        if (s2 > best2) { best2 = s2; bi2 = j; }
        if (s3 > best3) { best3 = s3; bi3 = j; }
    }

    int base = blockIdx.y * NTOK + tok0;
    g_partS[base + 0] = best0; g_partI[base + 0] = bi0;
    g_partS[base + 1] = best1; g_partI[base + 1] = bi1;
    g_partS[base + 2] = best2; g_partI[base + 2] = bi2;
    g_partS[base + 3] = best3; g_partI[base + 3] = bi3;
}

// ---------------------------------------------------------------------------
// K4: reduce argmax across splits (ascending code order, strict > keeps
//     first-index tie semantics).  Writes indices (as float) to output.
// ---------------------------------------------------------------------------
__global__ void k_argmin(float* __restrict__ out) {
    int token = blockIdx.x * 256 + threadIdx.x;
    float best = -3.4e38f;
    int bi = 0;
#pragma unroll
    for (int s = 0; s < NSPLIT; s++) {
        float v = g_partS[s * NTOK + token];
        int jj = g_partI[s * NTOK + token];
        if (v > best) { best = v; bi = s * CPS + jj; }
    }
    g_idx[token] = bi;
    out[IDX_OFF + token] = (float)bi;
}

// ---------------------------------------------------------------------------
// K5: out-projection.  grid(T/512, B, 16 o-splits of 64), 256 threads,
//     each thread owns 2 tokens packed as f32x2, 64-bit coalesced stores.
//     z_q_st = z_e + (codebook[idx] - z_e)  (exact straight-through value)
// ---------------------------------------------------------------------------
__global__ void __launch_bounds__(256) k_outproj(const float* __restrict__ cb,
                                                 float* __restrict__ out) {
    __shared__ unsigned long long s_w[64][8];
    __shared__ unsigned long long s_b[64];
    int tid = threadIdx.x;
    int ob = blockIdx.z * 64;
    for (int i = tid; i < 64 * 9; i += 256) {
        unsigned long long v = g_wdup[(size_t)ob * 9 + i];
        int j = i / 9, kk = i - j * 9;
        if (kk < 8) s_w[j][kk] = v; else s_b[j] = v;
    }

    int b = blockIdx.y;
    int t0 = blockIdx.x * 512 + tid * 2;
    int tk0 = b * TT + t0;
    int i0 = g_idx[tk0], i1 = g_idx[tk0 + 1];

    unsigned long long zq[8];
#pragma unroll
    for (int k = 0; k < 8; k++) {
        float ze0 = out[ZE_OFF + ((size_t)b * 8 + k) * TT + t0];
        float ze1 = out[ZE_OFF + ((size_t)b * 8 + k) * TT + t0 + 1];
        float q0 = cb[(size_t)i0 * CD + k];
        float q1 = cb[(size_t)i1 * CD + k];
        zq[k] = pack2(ze0 + (q0 - ze0), ze1 + (q1 - ze1));
    }
    __syncthreads();

    float* obase = out + OUT_OFF + ((size_t)b * DIN + ob) * TT + t0;
#pragma unroll 4
    for (int o = 0; o < 64; o++) {
        const ulonglong2* wp = reinterpret_cast<const ulonglong2*>(&s_w[o][0]);
        ulonglong2 wA = wp[0], wB = wp[1], wC = wp[2], wD = wp[3];
        unsigned long long acc = fma2(zq[0], wA.x, 0ull);
        acc = fma2(zq[1], wA.y, acc);
        acc = fma2(zq[2], wB.x, acc);
        acc = fma2(zq[3], wB.y, acc);
        acc = fma2(zq[4], wC.x, acc);
        acc = fma2(zq[5], wC.y, acc);
        acc = fma2(zq[6], wD.x, acc);
        acc = fma2(zq[7], wD.y, acc);
        acc = add2(acc, s_b[o]);
        *reinterpret_cast<unsigned long long*>(&obase[(size_t)o * TT]) = acc;
    }
}

// ---------------------------------------------------------------------------
extern "C" void kernel_launch(void* const* d_in, const int* in_sizes, int n_in,
                              void* d_out, int out_size) {
    const float* z     = (const float*)d_in[0];
    const float* w_in  = (const float*)d_in[1];
    const float* b_in  = (const float*)d_in[2];
    const float* w_out = (const float*)d_in[3];
    const float* b_out = (const float*)d_in[4];
    const float* cb    = (const float*)d_in[5];
    float* out = (float*)d_out;

    k_prep<<<(KCB + DIN + 16 + 255) / 256, 256>>>(cb, w_out, b_out, out);

    dim3 g1(TT / 256, BB, 8);
    k_inproj<<<g1, 256>>>(z, w_in);

    k_reduce<<<NTOK / 256, 256>>>(b_in, out);

    dim3 g3(NTOK / TOKBLK, NSPLIT);   // (16, 16)
    k_search<<<g3, 256>>>();

    k_argmin<<<NTOK / 256, 256>>>(out);

    dim3 g5(TT / 512, BB, DIN / 64);  // (4, 8, 16)
    k_outproj<<<g5, 256>>>(cb, out);
}

// round 4
// speedup vs baseline: 1.0512x; 1.0512x over previous
#include <cuda_runtime.h>

// Problem constants
#define BB      8
#define DIN     1024
#define TT      2048
#define KCB     8192
#define CD      8
#define NTOK    (BB*TT)            // 16384
#define NSPLIT  32
#define CPS     (KCB/NSPLIT)       // 256 codes per split
#define TOKBLK  1024               // tokens per search CTA (256 thr * 4 tok)

// Output buffer layout (float32, concatenated tuple)
#define OUT_OFF   0
#define LOSS_OFF  (BB*DIN*TT)                 // 16777216
#define IDX_OFF   (LOSS_OFF + 16)             // 16777232
#define ZE_OFF    (IDX_OFF + NTOK)            // 16793616

// Scratch (device globals — no allocation allowed)
__device__ float              g_zep[8u*BB*CD*TT];     // 4 MB partial in-proj [dc][b][o][t]
__device__ float              g_enc[(size_t)NTOK*CD]; // normalized encodings, token-major
__device__ unsigned long long g_cbdup[(size_t)KCB*9]; // per code: 8x {c,c} + {-c2/2,-c2/2}
__device__ unsigned long long g_wdup[(size_t)DIN*9];  // per out-row: 8x {w,w} + {b,b}
__device__ float              g_partS[NSPLIT*NTOK];
__device__ int                g_partI[NSPLIT*NTOK];
__device__ int                g_idx[NTOK];

// ---- packed f32x2 helpers ----
__device__ __forceinline__ unsigned long long pack2(float lo, float hi) {
    unsigned long long r;
    asm("mov.b64 %0, {%1,%2};" : "=l"(r) : "f"(lo), "f"(hi));
    return r;
}
__device__ __forceinline__ void unpack2(unsigned long long v, float& lo, float& hi) {
    asm("mov.b64 {%0,%1}, %2;" : "=f"(lo), "=f"(hi) : "l"(v));
}
__device__ __forceinline__ unsigned long long fma2(unsigned long long a, unsigned long long b,
                                                   unsigned long long c) {
    unsigned long long d;
    asm("fma.rn.f32x2 %0, %1, %2, %3;" : "=l"(d) : "l"(a), "l"(b), "l"(c));
    return d;
}
__device__ __forceinline__ unsigned long long add2(unsigned long long a, unsigned long long b) {
    unsigned long long d;
    asm("add.rn.f32x2 %0, %1, %2;" : "=l"(d) : "l"(a), "l"(b));
    return d;
}

// ---------------------------------------------------------------------------
// K0: prep — normalize codebook into duplicated-pair table, pack w_out/b_out,
//     zero the loss outputs.
// ---------------------------------------------------------------------------
__global__ void k_prep(const float* __restrict__ cb, const float* __restrict__ w_out,
                       const float* __restrict__ b_out, float* __restrict__ out) {
    int i = blockIdx.x * 256 + threadIdx.x;
    if (i < KCB) {
        float v[CD];
#pragma unroll
        for (int k = 0; k < CD; k++) v[k] = cb[(size_t)i * CD + k];
        float s = 0.0f;
#pragma unroll
        for (int k = 0; k < CD; k++) s += v[k] * v[k];
        float den = fmaxf(__fsqrt_rn(s), 1e-12f);
        float nv[CD];
#pragma unroll
        for (int k = 0; k < CD; k++) nv[k] = __fdiv_rn(v[k], den);
        float c2 = 0.0f;
#pragma unroll
        for (int k = 0; k < CD; k++) c2 += nv[k] * nv[k];
#pragma unroll
        for (int k = 0; k < CD; k++) g_cbdup[(size_t)i * 9 + k] = pack2(nv[k], nv[k]);
        float h = -0.5f * c2;
        g_cbdup[(size_t)i * 9 + 8] = pack2(h, h);
    } else if (i < KCB + DIN) {
        int o = i - KCB;
#pragma unroll
        for (int k = 0; k < CD; k++) {
            float w = w_out[(size_t)o * CD + k];
            g_wdup[(size_t)o * 9 + k] = pack2(w, w);
        }
        float bo = b_out[o];
        g_wdup[(size_t)o * 9 + 8] = pack2(bo, bo);
    } else if (i < KCB + DIN + 16) {
        out[LOSS_OFF + (i - KCB - DIN)] = 0.0f;
    }
}

// ---------------------------------------------------------------------------
// K1: partial in-projection.  grid(T/256, B, 8 d-chunks), 256 threads.
// ---------------------------------------------------------------------------
__global__ void __launch_bounds__(256) k_inproj(const float* __restrict__ z,
                                                const float* __restrict__ w_in) {
    __shared__ float sw[128 * 8];  // [dd][o]
    int tid = threadIdx.x;
    int tb = blockIdx.x, b = blockIdx.y, dc = blockIdx.z;
    for (int i = tid; i < 1024; i += 256) {
        int dd = i >> 3, o = i & 7;
        sw[dd * 8 + o] = w_in[(size_t)o * DIN + dc * 128 + dd];
    }
    __syncthreads();

    int t = tb * 256 + tid;
    float acc[8];
#pragma unroll
    for (int o = 0; o < 8; o++) acc[o] = 0.0f;

    const float* zp = z + ((size_t)b * DIN + (size_t)dc * 128) * TT + t;
#pragma unroll 4
    for (int dd = 0; dd < 128; dd++) {
        float zv = zp[(size_t)dd * TT];
        float4 wA = *reinterpret_cast<const float4*>(&sw[dd * 8]);
        float4 wB = *reinterpret_cast<const float4*>(&sw[dd * 8 + 4]);
        acc[0] += wA.x * zv; acc[1] += wA.y * zv; acc[2] += wA.z * zv; acc[3] += wA.w * zv;
        acc[4] += wB.x * zv; acc[5] += wB.y * zv; acc[6] += wB.z * zv; acc[7] += wB.w * zv;
    }
    float* op = g_zep + ((size_t)(dc * 8 + b) * 8) * TT + t;
#pragma unroll
    for (int o = 0; o < 8; o++) op[(size_t)o * TT] = acc[o];
}

// ---------------------------------------------------------------------------
// K2: reduce partials + bias, write z_e output, L2-normalize into g_enc.
// ---------------------------------------------------------------------------
__global__ void k_reduce(const float* __restrict__ b_in, float* __restrict__ out) {
    int token = blockIdx.x * 256 + threadIdx.x;   // 64 blocks
    int b = token >> 11, t = token & 2047;
    float ze[8];
#pragma unroll
    for (int o = 0; o < 8; o++) {
        float s = 0.0f;
#pragma unroll
        for (int dc = 0; dc < 8; dc++)
            s += g_zep[((size_t)(dc * 8 + b) * 8 + o) * TT + t];
        ze[o] = s + b_in[o];
    }
#pragma unroll
    for (int o = 0; o < 8; o++)
        out[ZE_OFF + ((size_t)b * 8 + o) * TT + t] = ze[o];
    float s2 = 0.0f;
#pragma unroll
    for (int o = 0; o < 8; o++) s2 += ze[o] * ze[o];
    float den = fmaxf(__fsqrt_rn(s2), 1e-12f);
#pragma unroll
    for (int o = 0; o < 8; o++)
        g_enc[(size_t)token * 8 + o] = __fdiv_rn(ze[o], den);
}

// ---------------------------------------------------------------------------
// K3: nearest-code search.  grid(16 token-blocks, 32 code-splits), 256 thr.
// Each thread: 4 tokens (two f32x2 pairs) x 256 codes.
// score = dot(enc_n, cb_n) - 0.5*c2  (argmax == reference argmin of dist)
// ---------------------------------------------------------------------------
__global__ void __launch_bounds__(256) k_search() {
    __shared__ unsigned long long s_cd[CPS][8];
    __shared__ unsigned long long s_c2[CPS];
    int tid = threadIdx.x;
    int cbase = blockIdx.y * CPS;

    for (int i = tid; i < CPS * 9; i += 256) {
        unsigned long long v = g_cbdup[(size_t)cbase * 9 + i];
        int j = i / 9, kk = i - j * 9;
        if (kk < 8) s_cd[j][kk] = v; else s_c2[j] = v;
    }

    int tok0 = blockIdx.x * TOKBLK + tid * 4;
    const float4* ep = reinterpret_cast<const float4*>(&g_enc[(size_t)tok0 * 8]);
    float4 p0 = ep[0], p1 = ep[1], p2 = ep[2], p3 = ep[3];
    float4 p4 = ep[4], p5 = ep[5], p6 = ep[6], p7 = ep[7];
    unsigned long long ea[8], eb[8];
    ea[0] = pack2(p0.x, p2.x); ea[1] = pack2(p0.y, p2.y);
    ea[2] = pack2(p0.z, p2.z); ea[3] = pack2(p0.w, p2.w);
    ea[4] = pack2(p1.x, p3.x); ea[5] = pack2(p1.y, p3.y);
    ea[6] = pack2(p1.z, p3.z); ea[7] = pack2(p1.w, p3.w);
    eb[0] = pack2(p4.x, p6.x); eb[1] = pack2(p4.y, p6.y);
    eb[2] = pack2(p4.z, p6.z); eb[3] = pack2(p4.w, p6.w);
    eb[4] = pack2(p5.x, p7.x); eb[5] = pack2(p5.y, p7.y);
    eb[6] = pack2(p5.z, p7.z); eb[7] = pack2(p5.w, p7.w);

    __syncthreads();

    float best0 = -3.4e38f, best1 = -3.4e38f, best2 = -3.4e38f, best3 = -3.4e38f;
    int bi0 = 0, bi1 = 0, bi2 = 0, bi3 = 0;

#pragma unroll 4
    for (int j = 0; j < CPS; j++) {
        unsigned long long c2p = s_c2[j];
        const ulonglong2* cp = reinterpret_cast<const ulonglong2*>(&s_cd[j][0]);
        ulonglong2 cA = cp[0], cB = cp[1], cC = cp[2], cD = cp[3];

        unsigned long long aA = fma2(ea[0], cA.x, c2p);
        unsigned long long aB = fma2(eb[0], cA.x, c2p);
        aA = fma2(ea[1], cA.y, aA);  aB = fma2(eb[1], cA.y, aB);
        aA = fma2(ea[2], cB.x, aA);  aB = fma2(eb[2], cB.x, aB);
        aA = fma2(ea[3], cB.y, aA);  aB = fma2(eb[3], cB.y, aB);
        aA = fma2(ea[4], cC.x, aA);  aB = fma2(eb[4], cC.x, aB);
        aA = fma2(ea[5], cC.y, aA);  aB = fma2(eb[5], cC.y, aB);
        aA = fma2(ea[6], cD.x, aA);  aB = fma2(eb[6], cD.x, aB);
        aA = fma2(ea[7], cD.y, aA);  aB = fma2(eb[7], cD.y, aB);

        float s0, s1, s2, s3;
        unpack2(aA, s0, s1);
        unpack2(aB, s2, s3);
        if (s0 > best0) { best0 = s0; bi0 = j; }
        if (s1 > best1) { best1 = s1; bi1 = j; }
        if (s2 > best2) { best2 = s2; bi2 = j; }
        if (s3 > best3) { best3 = s3; bi3 = j; }
    }

    int base = blockIdx.y * NTOK + tok0;
    g_partS[base + 0] = best0; g_partI[base + 0] = bi0;
    g_partS[base + 1] = best1; g_partI[base + 1] = bi1;
    g_partS[base + 2] = best2; g_partI[base + 2] = bi2;
    g_partS[base + 3] = best3; g_partI[base + 3] = bi3;
}

// ---------------------------------------------------------------------------
// K4: reduce argmax across splits (ascending code order, strict > keeps
//     first-index tie semantics).  Writes indices (as float) to output.
// ---------------------------------------------------------------------------
__global__ void k_argmin(float* __restrict__ out) {
    int token = blockIdx.x * 256 + threadIdx.x;
    float best = -3.4e38f;
    int bi = 0;
#pragma unroll
    for (int s = 0; s < NSPLIT; s++) {
        float v = g_partS[s * NTOK + token];
        int jj = g_partI[s * NTOK + token];
        if (v > best) { best = v; bi = s * CPS + jj; }
    }
    g_idx[token] = bi;
    out[IDX_OFF + token] = (float)bi;
}

// ---------------------------------------------------------------------------
// K5: out-projection.  grid(T/512, B, 16 o-splits of 64), 256 threads,
//     each thread owns 2 tokens packed as f32x2, 64-bit coalesced stores.
//     z_q_st = z_e + (codebook[idx] - z_e)  (exact straight-through value)
// ---------------------------------------------------------------------------
__global__ void __launch_bounds__(256) k_outproj(const float* __restrict__ cb,
                                                 float* __restrict__ out) {
    __shared__ unsigned long long s_w[64][8];
    __shared__ unsigned long long s_b[64];
    int tid = threadIdx.x;
    int ob = blockIdx.z * 64;
    for (int i = tid; i < 64 * 9; i += 256) {
        unsigned long long v = g_wdup[(size_t)ob * 9 + i];
        int j = i / 9, kk = i - j * 9;
        if (kk < 8) s_w[j][kk] = v; else s_b[j] = v;
    }

    int b = blockIdx.y;
    int t0 = blockIdx.x * 512 + tid * 2;
    int tk0 = b * TT + t0;
    int i0 = g_idx[tk0], i1 = g_idx[tk0 + 1];

    unsigned long long zq[8];
#pragma unroll
    for (int k = 0; k < 8; k++) {
        float ze0 = out[ZE_OFF + ((size_t)b * 8 + k) * TT + t0];
        float ze1 = out[ZE_OFF + ((size_t)b * 8 + k) * TT + t0 + 1];
        float q0 = cb[(size_t)i0 * CD + k];
        float q1 = cb[(size_t)i1 * CD + k];
        zq[k] = pack2(ze0 + (q0 - ze0), ze1 + (q1 - ze1));
    }
    __syncthreads();

    float* obase = out + OUT_OFF + ((size_t)b * DIN + ob) * TT + t0;
#pragma unroll 4
    for (int o = 0; o < 64; o++) {
        const ulonglong2* wp = reinterpret_cast<const ulonglong2*>(&s_w[o][0]);
        ulonglong2 wA = wp[0], wB = wp[1], wC = wp[2], wD = wp[3];
        unsigned long long acc = fma2(zq[0], wA.x, 0ull);
        acc = fma2(zq[1], wA.y, acc);
        acc = fma2(zq[2], wB.x, acc);
        acc = fma2(zq[3], wB.y, acc);
        acc = fma2(zq[4], wC.x, acc);
        acc = fma2(zq[5], wC.y, acc);
        acc = fma2(zq[6], wD.x, acc);
        acc = fma2(zq[7], wD.y, acc);
        acc = add2(acc, s_b[o]);
        *reinterpret_cast<unsigned long long*>(&obase[(size_t)o * TT]) = acc;
    }
}

// ---------------------------------------------------------------------------
extern "C" void kernel_launch(void* const* d_in, const int* in_sizes, int n_in,
                              void* d_out, int out_size) {
    const float* z     = (const float*)d_in[0];
    const float* w_in  = (const float*)d_in[1];
    const float* b_in  = (const float*)d_in[2];
    const float* w_out = (const float*)d_in[3];
    const float* b_out = (const float*)d_in[4];
    const float* cb    = (const float*)d_in[5];
    float* out = (float*)d_out;

    k_prep<<<(KCB + DIN + 16 + 255) / 256, 256>>>(cb, w_out, b_out, out);

    dim3 g1(TT / 256, BB, 8);
    k_inproj<<<g1, 256>>>(z, w_in);

    k_reduce<<<NTOK / 256, 256>>>(b_in, out);

    dim3 g3(NTOK / TOKBLK, NSPLIT);   // (16, 32)
    k_search<<<g3, 256>>>();

    k_argmin<<<NTOK / 256, 256>>>(out);

    dim3 g5(TT / 512, BB, DIN / 64);  // (4, 8, 16)
    k_outproj<<<g5, 256>>>(cb, out);
}